// round 9
// baseline (speedup 1.0000x reference)
#include <cuda_runtime.h>
#include <cstdint>

// x: [32, 512, 56, 56] fp32, chunks of 8 batches (51.4 MB, L2-resident).
// Single stream. Stage kernel fuses: scale chunk c (L2 reads + DRAM writes)
// + reduce-accumulate chunk c+1 (DRAM reads -> L2) as uniform per-thread work.
// DRAM total: 410 MB vs 616 MB.

#define C            512
#define CR           32
#define SPATIAL4     784                       // f4 per slice
#define SEGS_SLICE   196                       // 784/4 thread-segments per slice
#define CHUNK_B      8
#define NCHUNK       4
#define CHUNK_SLICES 4096
#define CHUNK_F4     (CHUNK_SLICES * SPATIAL4) // 3,211,264
#define NSEG         (CHUNK_F4 / 4)            // 802,816 segments
#define NBLK         (NSEG / 256)              // 3136

__device__ float d_sq[32 * C];                 // RAW sums (atomic-accumulated)
__device__ float d_e[32 * C];

// ---------------------------------------------------------------------------
// Plain reduce for chunk 0 (R1 shape, 6.28 TB/s proven). Writes RAW sums.
// ---------------------------------------------------------------------------
__global__ __launch_bounds__(128) void se_reduce0(const float* __restrict__ x)
{
    const int s = blockIdx.x;                  // slice in chunk 0
    const float4* __restrict__ p =
        reinterpret_cast<const float4*>(x) + (size_t)s * SPATIAL4;

    float acc = 0.0f;
    #pragma unroll
    for (int i = threadIdx.x; i < SPATIAL4; i += 128) {
        float4 v = p[i];
        acc += (v.x + v.y) + (v.z + v.w);
    }
    #pragma unroll
    for (int off = 16; off > 0; off >>= 1)
        acc += __shfl_down_sync(0xFFFFFFFFu, acc, off);

    __shared__ float ws[4];
    const int lane = threadIdx.x & 31;
    if (lane == 0) ws[threadIdx.x >> 5] = acc;
    __syncthreads();
    if (threadIdx.x == 0)
        d_sq[s] = ws[0] + ws[1] + ws[2] + ws[3];
}

// ---------------------------------------------------------------------------
// Excite chunk: batch per block. Reads RAW sums (scales by 1/3136), computes
// e, then ZEROES d_sq for this batch (replay-safe atomic accumulation).
// ---------------------------------------------------------------------------
__global__ __launch_bounds__(1024) void se_excite_chunk(
    const float* __restrict__ w1,
    const float* __restrict__ b1,
    const float* __restrict__ w2,
    const float* __restrict__ b2,
    int batch0)
{
    const int b    = batch0 + blockIdx.x;
    const int t    = threadIdx.x;
    const int wid  = t >> 5;
    const int lane = t & 31;

    __shared__ float sq[C];
    __shared__ float hid[CR];

    if (t < C) sq[t] = d_sq[b * C + t] * (1.0f / 3136.0f);
    __syncthreads();
    if (t < C) d_sq[b * C + t] = 0.0f;         // reset for next replay

    {
        const float* __restrict__ wrow = w1 + (size_t)wid * C;
        float acc = 0.0f;
        #pragma unroll
        for (int k = 0; k < 16; ++k) {
            const int idx = lane + 32 * k;
            acc = fmaf(sq[idx], wrow[idx], acc);
        }
        #pragma unroll
        for (int off = 16; off > 0; off >>= 1)
            acc += __shfl_down_sync(0xFFFFFFFFu, acc, off);
        if (lane == 0) hid[wid] = fmaxf(acc + b1[wid], 0.0f);
    }
    __syncthreads();

    if (t < C) {
        float acc = b2[t];
        const float* __restrict__ w2row = w2 + (size_t)t * CR;
        #pragma unroll
        for (int j = 0; j < CR; ++j)
            acc = fmaf(hid[j], w2row[j], acc);
        d_e[b * C + t] = 1.0f / (1.0f + __expf(-acc));
    }
}

// ---------------------------------------------------------------------------
// Fused stage: scale chunk sc (4 consecutive f4/thread, one e/thread,
// __ldcs reads + __stcs writes) and, if rc>=0, reduce-accumulate the same
// position of chunk rc (default-cached loads prime L2; segmented warp
// reduction + <=2 atomicAdds per warp into raw d_sq).
// ---------------------------------------------------------------------------
__global__ __launch_bounds__(256) void se_scale_accum(
    const float* __restrict__ x,
    float* __restrict__ out,
    int sc, int rc)
{
    const int seg  = blockIdx.x * 256 + threadIdx.x;   // 0..NSEG-1
    const int lane = threadIdx.x & 31;
    const int bc   = seg / SEGS_SLICE;                 // slice within chunk

    const float4* __restrict__ x4 = reinterpret_cast<const float4*>(x);
    float4*       __restrict__ o4 = reinterpret_cast<float4*>(out);

    const unsigned int base_s = (unsigned int)sc * CHUNK_F4 + (unsigned int)seg * 4u;

    // batched loads: 4 scale f4 (+4 reduce f4) in flight together
    float4 vs[4];
    #pragma unroll
    for (int j = 0; j < 4; ++j)
        vs[j] = __ldcs(x4 + base_s + j);

    float4 vr[4];
    unsigned int base_r = 0;
    if (rc >= 0) {
        base_r = (unsigned int)rc * CHUNK_F4 + (unsigned int)seg * 4u;
        #pragma unroll
        for (int j = 0; j < 4; ++j)
            vr[j] = x4[base_r + j];                    // default: keep in L2
    }

    const float e = __ldg(&d_e[sc * CHUNK_SLICES + bc]);
    #pragma unroll
    for (int j = 0; j < 4; ++j) {
        float4 r = vs[j];
        r.x *= e; r.y *= e; r.z *= e; r.w *= e;
        __stcs(o4 + base_s + j, r);
    }

    if (rc >= 0) {
        float s = 0.0f;
        #pragma unroll
        for (int j = 0; j < 4; ++j)
            s += (vr[j].x + vr[j].y) + (vr[j].z + vr[j].w);

        // head-segmented warp reduction keyed by bc (keys contiguous in-warp)
        int key = bc;
        #pragma unroll
        for (int off = 16; off > 0; off >>= 1) {
            const float v2 = __shfl_down_sync(0xFFFFFFFFu, s, off);
            const int   k2 = __shfl_down_sync(0xFFFFFFFFu, key, off);
            if (lane + off < 32 && k2 == key) s += v2;
        }
        const int keyprev = __shfl_up_sync(0xFFFFFFFFu, key, 1);
        if (lane == 0 || keyprev != key)
            atomicAdd(&d_sq[rc * CHUNK_SLICES + bc], s);
    }
}

// ---------------------------------------------------------------------------
extern "C" void kernel_launch(void* const* d_in, const int* in_sizes, int n_in,
                              void* d_out, int out_size) {
    const float* x  = (const float*)d_in[0];
    const float* w1 = (const float*)d_in[1];
    const float* b1 = (const float*)d_in[2];
    const float* w2 = (const float*)d_in[3];
    const float* b2 = (const float*)d_in[4];
    float* out = (float*)d_out;

    se_reduce0<<<CHUNK_SLICES, 128>>>(x);
    for (int c = 0; c < NCHUNK; ++c) {
        se_excite_chunk<<<CHUNK_B, 1024>>>(w1, b1, w2, b2, c * CHUNK_B);
        const int rc = (c + 1 < NCHUNK) ? c + 1 : -1;
        se_scale_accum<<<NBLK, 256>>>(x, out, c, rc);
    }
}